// round 5
// baseline (speedup 1.0000x reference)
#include <cuda_runtime.h>
#include <math.h>
#include <stdint.h>

// Problem constants (fixed by the dataset)
#define NB        16384          // number of 3x3 blocks
#define BDIM      (3 * NB)       // 49152 floats per row of x
#define BDIM_F4   (BDIM / 4)     // 12288 float4 per row
#define BATCH     4096

#define THREADS            256
#define F4_PER_THREAD      3                         // 12 floats per thread
#define F4_PER_CTA         (THREADS * F4_PER_THREAD) // 768 float4 = 12KB chunk
#define COL_TILES          (BDIM_F4 / F4_PER_CTA)    // 16
#define ROWS_PER_CTA       16
#define ROW_GROUPS         (BATCH / ROWS_PER_CTA)    // 256

// Transposed weights: for each x-column j, the 3-vector it feeds into out:
//   g_WT[j*3 + k] = W(j/3)[k][j%3],  k = 0..2
// 49152 * 3 floats = 589,824 B
__device__ float g_WT[BDIM * 3];

__device__ __forceinline__ float softplus_f(float v) {
    return (v > 20.0f) ? v : log1pf(expf(v));
}

// Builds transposed W AND zeroes the (poisoned) output buffer.
__global__ void build_w_kernel(const float* __restrict__ w, float* __restrict__ out,
                               int out_n) {
    int n = blockIdx.x * blockDim.x + threadIdx.x;
    if (n < out_n) out[n] = 0.0f;
    if (n >= NB) return;
    float w0 = w[n * 6 + 0], w1 = w[n * 6 + 1], w2 = w[n * 6 + 2];
    float w3 = w[n * 6 + 3], w4 = w[n * 6 + 4], w5 = w[n * 6 + 5];

    float a = softplus_f(w0);   // M00
    float b = w1, c = w2;       // M01, M02
    float d = softplus_f(w3);   // M11
    float e = w4;               // M12
    float f = softplus_f(w5);   // M22

    // symmetric W = M^T M
    float W00 = a * a;
    float W01 = a * b;
    float W02 = a * c;
    float W11 = b * b + d * d;
    float W12 = b * c + d * e;
    float W22 = c * c + e * e + f * f;

    // columns of W for x-columns 3n, 3n+1, 3n+2
    float* p = g_WT + (size_t)n * 9;
    p[0] = W00; p[1] = W01; p[2] = W02;   // col 0
    p[3] = W01; p[4] = W11; p[5] = W12;   // col 1
    p[6] = W02; p[7] = W12; p[8] = W22;   // col 2
}

__global__ void __launch_bounds__(THREADS, 4)
main_kernel(const float* __restrict__ x, float* __restrict__ out) {
    const int t    = threadIdx.x;
    const int lane = t & 31;
    const int tile = blockIdx.x;
    const int row0 = blockIdx.y * ROWS_PER_CTA;

    // this thread's 3 float4 positions within a row (lane-interleaved, coalesced)
    const int g0 = tile * F4_PER_CTA + t;   // +0, +256, +512

    // ---- W for this thread's 12 columns -> 36 regs, reused across 16 rows ----
    // WT float4 index for x-float4 g is 3g..3g+2 (12 floats per x-float4)
    float w[F4_PER_THREAD * 12];
    {
        const float4* wp = reinterpret_cast<const float4*>(g_WT);
        #pragma unroll
        for (int i = 0; i < F4_PER_THREAD; ++i) {
            int base = 3 * (g0 + THREADS * i);
            #pragma unroll
            for (int k = 0; k < 3; ++k) {
                float4 v = wp[base + k];
                w[i * 12 + k * 4 + 0] = v.x;
                w[i * 12 + k * 4 + 1] = v.y;
                w[i * 12 + k * 4 + 2] = v.z;
                w[i * 12 + k * 4 + 3] = v.w;
            }
        }
    }

    const float4* xb = reinterpret_cast<const float4*>(x) +
                       (size_t)row0 * BDIM_F4 + g0;

    for (int r = 0; r < ROWS_PER_CTA; ++r) {
        const float4* xr = xb + (size_t)r * BDIM_F4;

        // 3 independent coalesced LDG.128 (1 wavefront per 128B line)
        float4 v0 = xr[0];
        float4 v1 = xr[THREADS];
        float4 v2 = xr[2 * THREADS];

        float xv[12] = { v0.x, v0.y, v0.z, v0.w,
                         v1.x, v1.y, v1.z, v1.w,
                         v2.x, v2.y, v2.z, v2.w };

        float s0 = 0.0f, s1 = 0.0f, s2 = 0.0f;
        #pragma unroll
        for (int i = 0; i < F4_PER_THREAD; ++i) {
            #pragma unroll
            for (int c = 0; c < 4; ++c) {
                float xe = xv[i * 4 + c];
                s0 = fmaf(w[i * 12 + 3 * c + 0], xe, s0);
                s1 = fmaf(w[i * 12 + 3 * c + 1], xe, s1);
                s2 = fmaf(w[i * 12 + 3 * c + 2], xe, s2);
            }
        }

        // warp tree-reduce, lane 0 -> global RED (no CTA sync anywhere)
        #pragma unroll
        for (int off = 16; off; off >>= 1) {
            s0 += __shfl_down_sync(0xffffffffu, s0, off);
            s1 += __shfl_down_sync(0xffffffffu, s1, off);
            s2 += __shfl_down_sync(0xffffffffu, s2, off);
        }
        if (lane == 0) {
            const int row = row0 + r;
            atomicAdd(&out[row * 3 + 0], s0);
            atomicAdd(&out[row * 3 + 1], s1);
            atomicAdd(&out[row * 3 + 2], s2);
        }
    }
}

extern "C" void kernel_launch(void* const* d_in, const int* in_sizes, int n_in,
                              void* d_out, int out_size) {
    const float* x      = (const float*)d_in[0];   // [4096, 49152] f32
    const float* weight = (const float*)d_in[1];   // [16384, 6]    f32
    float* out          = (float*)d_out;           // [4096, 3]     f32

    // 1) build transposed W + zero the poisoned output (atomics accumulate)
    build_w_kernel<<<(NB + 255) / 256, 256>>>(weight, out, out_size);

    // 2) pure register-streaming blocked reduction
    dim3 grid(COL_TILES, ROW_GROUPS);
    main_kernel<<<grid, THREADS>>>(x, out);
}

// round 6
// speedup vs baseline: 1.1940x; 1.1940x over previous
#include <cuda_runtime.h>
#include <math.h>
#include <stdint.h>

// Problem constants (fixed by the dataset)
#define NB        16384
#define BDIM      (3 * NB)        // 49152 floats per row
#define BDIM_F4   (BDIM / 4)      // 12288 float4 per row
#define BATCH     4096

#define THREADS       256
#define ROWS_PT       8                           // rows accumulated per thread
#define CHUNKS        6                           // column chunks per CTA
#define F4_PER_TILE   (THREADS * CHUNKS)          // 1536 float4
#define COL_TILES     (BDIM_F4 / F4_PER_TILE)     // 8
#define ROW_GROUPS    (BATCH / ROWS_PT)           // 512

// Transposed weights: g_WT[j*3 + k] = W(j/3)[k][j%3]  (j = x column)
__device__ float g_WT[BDIM * 3];

__device__ __forceinline__ float softplus_f(float v) {
    return (v > 20.0f) ? v : log1pf(expf(v));
}

// Builds transposed W AND zeroes the (poisoned) output buffer.
__global__ void build_w_kernel(const float* __restrict__ w, float* __restrict__ out,
                               int out_n) {
    int n = blockIdx.x * blockDim.x + threadIdx.x;
    if (n < out_n) out[n] = 0.0f;
    if (n >= NB) return;
    float w0 = w[n * 6 + 0], w1 = w[n * 6 + 1], w2 = w[n * 6 + 2];
    float w3 = w[n * 6 + 3], w4 = w[n * 6 + 4], w5 = w[n * 6 + 5];

    float a = softplus_f(w0);
    float b = w1, c = w2;
    float d = softplus_f(w3);
    float e = w4;
    float f = softplus_f(w5);

    float W00 = a * a;
    float W01 = a * b;
    float W02 = a * c;
    float W11 = b * b + d * d;
    float W12 = b * c + d * e;
    float W22 = c * c + e * e + f * f;

    float* p = g_WT + (size_t)n * 9;
    p[0] = W00; p[1] = W01; p[2] = W02;   // x-col 3n
    p[3] = W01; p[4] = W11; p[5] = W12;   // x-col 3n+1
    p[6] = W02; p[7] = W12; p[8] = W22;   // x-col 3n+2
}

__global__ void __launch_bounds__(THREADS, 2)
main_kernel(const float* __restrict__ x, float* __restrict__ out) {
    const int t    = threadIdx.x;
    const int lane = t & 31;
    const int tile = blockIdx.x;
    const int row0 = blockIdx.y * ROWS_PT;

    const float4* x4 = reinterpret_cast<const float4*>(x);
    const float4* wp = reinterpret_cast<const float4*>(g_WT);

    // 8 rows x 3 outputs accumulated in registers; reduced ONCE at the end.
    float acc[ROWS_PT * 3];
    #pragma unroll
    for (int i = 0; i < ROWS_PT * 3; ++i) acc[i] = 0.0f;

    const int gbase = tile * F4_PER_TILE + t;

    for (int c = 0; c < CHUNKS; ++c) {
        const int g = gbase + c * THREADS;      // this thread's float4 column index

        // 8 independent coalesced x loads (different rows, same column)
        const float4* xp = x4 + (size_t)row0 * BDIM_F4 + g;
        float4 xr[ROWS_PT];
        #pragma unroll
        for (int r = 0; r < ROWS_PT; ++r)
            xr[r] = xp[(size_t)r * BDIM_F4];

        // 12 W floats for these 4 x-columns (L2-resident)
        float4 w0 = wp[3 * g + 0];
        float4 w1 = wp[3 * g + 1];
        float4 w2 = wp[3 * g + 2];
        float wf[12] = { w0.x, w0.y, w0.z, w0.w,
                         w1.x, w1.y, w1.z, w1.w,
                         w2.x, w2.y, w2.z, w2.w };

        #pragma unroll
        for (int r = 0; r < ROWS_PT; ++r) {
            float xc[4] = { xr[r].x, xr[r].y, xr[r].z, xr[r].w };
            #pragma unroll
            for (int cc = 0; cc < 4; ++cc) {
                acc[r * 3 + 0] = fmaf(wf[cc * 3 + 0], xc[cc], acc[r * 3 + 0]);
                acc[r * 3 + 1] = fmaf(wf[cc * 3 + 1], xc[cc], acc[r * 3 + 1]);
                acc[r * 3 + 2] = fmaf(wf[cc * 3 + 2], xc[cc], acc[r * 3 + 2]);
            }
        }
    }

    // One warp tree-reduce for all 24 accumulators (off the streaming path)
    #pragma unroll
    for (int off = 16; off; off >>= 1) {
        #pragma unroll
        for (int i = 0; i < ROWS_PT * 3; ++i)
            acc[i] += __shfl_down_sync(0xffffffffu, acc[i], off);
    }
    if (lane == 0) {
        #pragma unroll
        for (int r = 0; r < ROWS_PT; ++r) {
            atomicAdd(&out[(row0 + r) * 3 + 0], acc[r * 3 + 0]);
            atomicAdd(&out[(row0 + r) * 3 + 1], acc[r * 3 + 1]);
            atomicAdd(&out[(row0 + r) * 3 + 2], acc[r * 3 + 2]);
        }
    }
}

extern "C" void kernel_launch(void* const* d_in, const int* in_sizes, int n_in,
                              void* d_out, int out_size) {
    const float* x      = (const float*)d_in[0];   // [4096, 49152] f32
    const float* weight = (const float*)d_in[1];   // [16384, 6]    f32
    float* out          = (float*)d_out;           // [4096, 3]     f32

    // 1) build transposed W + zero the poisoned output (atomics accumulate)
    build_w_kernel<<<(NB + 255) / 256, 256>>>(weight, out, out_size);

    // 2) multi-row register accumulation, reduction off the critical path
    dim3 grid(COL_TILES, ROW_GROUPS);
    main_kernel<<<grid, THREADS>>>(x, out);
}